// round 1
// baseline (speedup 1.0000x reference)
#include <cuda_runtime.h>

// ---------------- problem constants ----------------
#define N_IMG   512
#define C_CH    3
#define SDIM    224
#define NPATCH  16
#define PS      14
#define INPUT_D 588        // 3*14*14
#define HID     8
#define HEADS   2
#define DH      4
#define SEQ     257
#define MLPD    32
#define DIMOUT  10
#define EPS_LN  1e-5f

// scratch: token/state buffer x[n][257][8]
__device__ float g_x[N_IMG * SEQ * HID];

// ======================================================================
// Kernel A: patchify + linear proj + pos embed + cls token
// grid (16, 512) = (py, n), 128 threads: thread = (patch_x p = tid>>3, slice s = tid&7)
// ======================================================================
__global__ void __launch_bounds__(128) patch_embed_kernel(
    const float* __restrict__ images, const int* __restrict__ labels,
    const float* __restrict__ Wm, const float* __restrict__ bm,
    const float* __restrict__ cls_table, const float* __restrict__ pe)
{
    __shared__ float wm_s[INPUT_D * HID];   // 18816 B

    const int py  = blockIdx.x;
    const int n   = blockIdx.y;
    const int tid = threadIdx.x;

    for (int i = tid; i < INPUT_D * HID; i += 128) wm_s[i] = Wm[i];
    __syncthreads();

    const int p = tid >> 3;   // patch_x 0..15
    const int s = tid & 7;    // d-slice  0..7

    const float* img = images + (size_t)n * (C_CH * SDIM * SDIM)
                              + (size_t)(py * PS) * SDIM + p * PS;

    float acc[8];
#pragma unroll
    for (int e = 0; e < 8; e++) acc[e] = 0.f;

    // walk d = s, s+8, ... < 588 with incremental (c,r,q) -> gmem offset
    int q = s, r = 0;
    int off = s;                     // c*50176 + r*224 + q
    for (int d = s; d < INPUT_D; d += 8) {
        float xv = __ldg(img + off);
        const float4* w4 = reinterpret_cast<const float4*>(wm_s + d * 8);
        float4 w0 = w4[0], w1 = w4[1];
        acc[0] += xv * w0.x; acc[1] += xv * w0.y;
        acc[2] += xv * w0.z; acc[3] += xv * w0.w;
        acc[4] += xv * w1.x; acc[5] += xv * w1.y;
        acc[6] += xv * w1.z; acc[7] += xv * w1.w;
        q += 8; off += 8;
        if (q >= PS) {               // row wrap
            q -= PS; off += (SDIM - PS);
            r++;
            if (r >= PS) { r = 0; off += (SDIM * SDIM - PS * SDIM); }
        }
    }

    // reduce the 8 d-slices of each patch (lanes grouped by 8)
#pragma unroll
    for (int o2 = 4; o2; o2 >>= 1)
#pragma unroll
        for (int e = 0; e < 8; e++)
            acc[e] += __shfl_xor_sync(0xffffffffu, acc[e], o2);

    if (s == 0) {
        const int tok = 1 + py * 16 + p;
        float*       dst = g_x + ((size_t)n * SEQ + tok) * HID;
        const float* per = pe + tok * HID;
#pragma unroll
        for (int e = 0; e < 8; e++) dst[e] = acc[e] + __ldg(bm + e) + __ldg(per + e);
    }
    if (py == 0 && tid < 8) {
        int lab = labels[n];
        g_x[(size_t)n * SEQ * HID + tid] = cls_table[lab * 8 + tid] + pe[tid];
    }
}

// ======================================================================
// Kernel B: full 2-layer transformer + head, one block per image
// 512 blocks, 256 threads. Everything lives in SMEM.
// ======================================================================

// ws layout offsets
#define W_LN1G 0
#define W_LN1B 8
#define W_WQ   16
#define W_BQ   48
#define W_WK   56
#define W_BK   88
#define W_WV   96
#define W_BV   128
#define W_LN2G 136
#define W_LN2B 144
#define W_W1   152
#define W_B1   408
#define W_W2   440
#define W_B2   696

__global__ void __launch_bounds__(256) vit_blocks_kernel(
    const float* __restrict__ ln1_g, const float* __restrict__ ln1_b,
    const float* __restrict__ Wq, const float* __restrict__ bq,
    const float* __restrict__ Wk, const float* __restrict__ bk,
    const float* __restrict__ Wv, const float* __restrict__ bv,
    const float* __restrict__ ln2_g, const float* __restrict__ ln2_b,
    const float* __restrict__ W1, const float* __restrict__ b1,
    const float* __restrict__ W2, const float* __restrict__ b2,
    const float* __restrict__ Wf, const float* __restrict__ bf,
    float* __restrict__ out)
{
    __shared__ float  xs[SEQ * 9];        // row stride 9 to dodge bank conflicts
    __shared__ float4 q4[2 * SEQ];
    __shared__ float4 k4[2 * SEQ];
    __shared__ float4 v4[2 * SEQ];
    __shared__ float  ws[704];

    const int n   = blockIdx.x;
    const int tid = threadIdx.x;

    for (int i = tid; i < SEQ * HID; i += 256)
        xs[(i >> 3) * 9 + (i & 7)] = g_x[(size_t)n * SEQ * HID + i];

    for (int l = 0; l < 2; l++) {
        __syncthreads();
        // ---- stage per-layer weights into SMEM ----
        if (tid < 8) {
            ws[W_LN1G + tid] = ln1_g[l * 8 + tid];
            ws[W_LN1B + tid] = ln1_b[l * 8 + tid];
            ws[W_BQ   + tid] = bq[l * 8 + tid];
            ws[W_BK   + tid] = bk[l * 8 + tid];
            ws[W_BV   + tid] = bv[l * 8 + tid];
            ws[W_LN2G + tid] = ln2_g[l * 8 + tid];
            ws[W_LN2B + tid] = ln2_b[l * 8 + tid];
            ws[W_B2   + tid] = b2[l * 8 + tid];
        }
        if (tid < 32) {
            ws[W_WQ + tid] = Wq[l * 32 + tid];
            ws[W_WK + tid] = Wk[l * 32 + tid];
            ws[W_WV + tid] = Wv[l * 32 + tid];
            ws[W_B1 + tid] = b1[l * 32 + tid];
        }
        ws[W_W1 + tid] = W1[l * 256 + tid];
        ws[W_W2 + tid] = W2[l * 256 + tid];
        __syncthreads();

        // ---- LN1 + QKV ----
        for (int t = tid; t < SEQ; t += 256) {
            float x8[8]; float m = 0.f;
#pragma unroll
            for (int e = 0; e < 8; e++) { x8[e] = xs[t * 9 + e]; m += x8[e]; }
            m *= 0.125f;
            float var = 0.f;
#pragma unroll
            for (int e = 0; e < 8; e++) { float dd = x8[e] - m; var += dd * dd; }
            float inv = rsqrtf(var * 0.125f + EPS_LN);
            float h[8];
#pragma unroll
            for (int e = 0; e < 8; e++)
                h[e] = (x8[e] - m) * inv * ws[W_LN1G + e] + ws[W_LN1B + e];
#pragma unroll
            for (int hh = 0; hh < 2; hh++) {
                float qv[4], kv[4], vv[4];
#pragma unroll
                for (int e = 0; e < 4; e++) {
                    qv[e] = ws[W_BQ + hh * 4 + e];
                    kv[e] = ws[W_BK + hh * 4 + e];
                    vv[e] = ws[W_BV + hh * 4 + e];
                }
#pragma unroll
                for (int d = 0; d < 4; d++) {
                    float hv = h[hh * 4 + d];
#pragma unroll
                    for (int e = 0; e < 4; e++) {
                        qv[e] += hv * ws[W_WQ + hh * 16 + d * 4 + e];
                        kv[e] += hv * ws[W_WK + hh * 16 + d * 4 + e];
                        vv[e] += hv * ws[W_WV + hh * 16 + d * 4 + e];
                    }
                }
                q4[hh * SEQ + t] = make_float4(qv[0], qv[1], qv[2], qv[3]);
                k4[hh * SEQ + t] = make_float4(kv[0], kv[1], kv[2], kv[3]);
                v4[hh * SEQ + t] = make_float4(vv[0], vv[1], vv[2], vv[3]);
            }
        }
        __syncthreads();

        // ---- attention: one thread per (head, query row); logits tiny -> no max sub ----
        for (int row = tid; row < 2 * SEQ; row += 256) {
            const int hh   = (row >= SEQ) ? 1 : 0;
            const int sidx = row - hh * SEQ;
            const float4 qv = q4[hh * SEQ + sidx];
            const float4* kb = k4 + hh * SEQ;
            const float4* vb = v4 + hh * SEQ;
            float  ssum = 0.f;
            float4 o = make_float4(0.f, 0.f, 0.f, 0.f);
            for (int t = 0; t < SEQ; t++) {
                float4 kt = kb[t];
                float dot = qv.x * kt.x + qv.y * kt.y + qv.z * kt.z + qv.w * kt.w;
                float pp = __expf(dot * 0.5f);
                float4 vt = vb[t];
                o.x += pp * vt.x; o.y += pp * vt.y;
                o.z += pp * vt.z; o.w += pp * vt.w;
                ssum += pp;
            }
            float invs = 1.f / ssum;
            float* xr = xs + sidx * 9 + hh * 4;
            xr[0] += o.x * invs; xr[1] += o.y * invs;
            xr[2] += o.z * invs; xr[3] += o.w * invs;
        }
        __syncthreads();

        // ---- LN2 + MLP (exact GELU) ----
        for (int t = tid; t < SEQ; t += 256) {
            float x8[8]; float m = 0.f;
#pragma unroll
            for (int e = 0; e < 8; e++) { x8[e] = xs[t * 9 + e]; m += x8[e]; }
            m *= 0.125f;
            float var = 0.f;
#pragma unroll
            for (int e = 0; e < 8; e++) { float dd = x8[e] - m; var += dd * dd; }
            float inv = rsqrtf(var * 0.125f + EPS_LN);
            float h[8];
#pragma unroll
            for (int e = 0; e < 8; e++)
                h[e] = (x8[e] - m) * inv * ws[W_LN2G + e] + ws[W_LN2B + e];
            float o8[8];
#pragma unroll
            for (int e = 0; e < 8; e++) o8[e] = ws[W_B2 + e];
#pragma unroll
            for (int j = 0; j < MLPD; j++) {
                float a = ws[W_B1 + j];
#pragma unroll
                for (int d = 0; d < 8; d++) a += h[d] * ws[W_W1 + d * 32 + j];
                float g = 0.5f * a * (1.f + erff(a * 0.70710678118f));
#pragma unroll
                for (int e = 0; e < 8; e++) o8[e] += g * ws[W_W2 + j * 8 + e];
            }
#pragma unroll
            for (int e = 0; e < 8; e++) xs[t * 9 + e] = x8[e] + o8[e];
        }
    }
    __syncthreads();

    // ---- head: out[n] = x[0] @ Wf + bf ----
    if (tid < DIMOUT) {
        float a = bf[tid];
#pragma unroll
        for (int e = 0; e < 8; e++) a += xs[e] * Wf[e * DIMOUT + tid];
        out[n * DIMOUT + tid] = a;
    }
}

// ======================================================================
extern "C" void kernel_launch(void* const* d_in, const int* in_sizes, int n_in,
                              void* d_out, int out_size)
{
    const float* images    = (const float*)d_in[0];
    const int*   labels    = (const int*)  d_in[1];
    const float* Wm        = (const float*)d_in[2];
    const float* bm        = (const float*)d_in[3];
    const float* cls_table = (const float*)d_in[4];
    const float* pe        = (const float*)d_in[5];
    const float* ln1_g     = (const float*)d_in[6];
    const float* ln1_b     = (const float*)d_in[7];
    const float* Wq        = (const float*)d_in[8];
    const float* bq        = (const float*)d_in[9];
    const float* Wk        = (const float*)d_in[10];
    const float* bk        = (const float*)d_in[11];
    const float* Wv        = (const float*)d_in[12];
    const float* bv        = (const float*)d_in[13];
    const float* ln2_g     = (const float*)d_in[14];
    const float* ln2_b     = (const float*)d_in[15];
    const float* W1        = (const float*)d_in[16];
    const float* b1        = (const float*)d_in[17];
    const float* W2        = (const float*)d_in[18];
    const float* b2        = (const float*)d_in[19];
    const float* Wf        = (const float*)d_in[20];
    const float* bf        = (const float*)d_in[21];
    float* out = (float*)d_out;

    dim3 gridA(NPATCH, N_IMG);
    patch_embed_kernel<<<gridA, 128>>>(images, labels, Wm, bm, cls_table, pe);

    vit_blocks_kernel<<<N_IMG, 256>>>(ln1_g, ln1_b, Wq, bq, Wk, bk, Wv, bv,
                                      ln2_g, ln2_b, W1, b1, W2, b2, Wf, bf, out);
}

// round 2
// speedup vs baseline: 1.5549x; 1.5549x over previous
#include <cuda_runtime.h>

// ---------------- problem constants ----------------
#define N_IMG   512
#define C_CH    3
#define SDIM    224
#define NPATCH  16
#define PS      14
#define INPUT_D 588        // 3*14*14
#define HID     8
#define HEADS   2
#define DH      4
#define SEQ     257
#define MLPD    32
#define DIMOUT  10
#define EPS_LN  1e-5f

// scratch: token/state buffer x[n][257][8]
__device__ float g_x[N_IMG * SEQ * HID];

// ======================================================================
// Kernel A v2: patchify + linear proj + pos embed + cls token
// grid (16, 512) = (py, n), 128 threads.
// Image stripe staged to SMEM via coalesced float4; each thread computes
// 4 patches x 8 hid over a (s,dq) slice of d, so each 32B weight row feeds
// 32 FMAs. Reduce over s via shfl, over dq via smem.
// thread: dq = warp (0..3), lane = s*4 + pg  (s 0..7 d-slice, pg 0..3 patch grp)
// ======================================================================
__global__ void __launch_bounds__(128) patch_embed_kernel(
    const float* __restrict__ images, const int* __restrict__ labels,
    const float* __restrict__ Wm, const float* __restrict__ bm,
    const float* __restrict__ cls_table, const float* __restrict__ pe)
{
    __shared__ float wm_s[INPUT_D * HID];   // 18816 B, layout d*8+e
    __shared__ float xstripe[PS * SDIM];    // one channel stripe, 12544 B
    __shared__ float sacc[4][16 * 9];       // dq-partials, stride-9 pad

    const int py  = blockIdx.x;
    const int n   = blockIdx.y;
    const int tid = threadIdx.x;
    const int lane = tid & 31;
    const int dq   = tid >> 5;     // 0..3 (warp id)
    const int pg   = lane & 3;     // 0..3
    const int s    = lane >> 2;    // 0..7

    // stage Wm with float4 (1176 vec loads)
    {
        const float4* src = reinterpret_cast<const float4*>(Wm);
        float4*       dst = reinterpret_cast<float4*>(wm_s);
        for (int i = tid; i < INPUT_D * HID / 4; i += 128) dst[i] = src[i];
    }

    float acc[4][8];
#pragma unroll
    for (int j = 0; j < 4; j++)
#pragma unroll
        for (int e = 0; e < 8; e++) acc[j][e] = 0.f;

    const float* imgbase = images + (size_t)n * (C_CH * SDIM * SDIM) + py * (PS * SDIM);

    for (int c = 0; c < C_CH; c++) {
        __syncthreads();
        // stage channel stripe: 3136 contiguous floats = 784 float4
        {
            const float4* src = reinterpret_cast<const float4*>(imgbase + c * (SDIM * SDIM));
            float4*       dst = reinterpret_cast<float4*>(xstripe);
            for (int i = tid; i < PS * SDIM / 4; i += 128) dst[i] = src[i];
        }
        __syncthreads();

        // d_local = (dq*7 + k)*8 + s, k = 0..6 ; covers 0..223 (>=196 guarded)
        int dl = dq * 56 + s;
        int r  = dl / PS;
        int q  = dl - r * PS;
        for (int k = 0; k < 7; k++) {
            if (dl < 196) {
                const float4* w4 = reinterpret_cast<const float4*>(wm_s + (c * 196 + dl) * 8);
                float4 w0 = w4[0], w1 = w4[1];
                int base = r * SDIM + q;
#pragma unroll
                for (int j = 0; j < 4; j++) {
                    float xv = xstripe[base + (pg + 4 * j) * PS];
                    acc[j][0] += xv * w0.x; acc[j][1] += xv * w0.y;
                    acc[j][2] += xv * w0.z; acc[j][3] += xv * w0.w;
                    acc[j][4] += xv * w1.x; acc[j][5] += xv * w1.y;
                    acc[j][6] += xv * w1.z; acc[j][7] += xv * w1.w;
                }
            }
            dl += 8; q += 8;
            if (q >= PS) { q -= PS; r++; }
        }
    }

    // reduce over s (lane bits 2..4): xor offsets 4,8,16
#pragma unroll
    for (int off = 16; off >= 4; off >>= 1)
#pragma unroll
        for (int j = 0; j < 4; j++)
#pragma unroll
            for (int e = 0; e < 8; e++)
                acc[j][e] += __shfl_xor_sync(0xffffffffu, acc[j][e], off);

    if (s == 0) {   // lanes 0..3 hold s-sums
#pragma unroll
        for (int j = 0; j < 4; j++) {
            int p = pg + 4 * j;
#pragma unroll
            for (int e = 0; e < 8; e++) sacc[dq][p * 9 + e] = acc[j][e];
        }
    }
    __syncthreads();

    // final dq-sum + bias + pos-embed, 128 threads = (p, e)
    {
        int p = tid >> 3, e = tid & 7;
        float sum = sacc[0][p * 9 + e] + sacc[1][p * 9 + e]
                  + sacc[2][p * 9 + e] + sacc[3][p * 9 + e];
        int tok = 1 + py * 16 + p;
        g_x[((size_t)n * SEQ + tok) * HID + e] = sum + __ldg(bm + e) + __ldg(pe + tok * 8 + e);
    }
    if (py == 0 && tid < 8) {
        int lab = labels[n];
        g_x[(size_t)n * SEQ * HID + tid] = cls_table[lab * 8 + tid] + pe[tid];
    }
}

// ======================================================================
// Kernel B v2: full 2-layer transformer + head, one block per image.
// launch_bounds(256,2) for 2 CTAs/SM. Layer 2 only needs token 0 downstream:
// attention computes 2 query rows cooperatively; MLP only token 0.
// ======================================================================

#define W_LN1G 0
#define W_LN1B 8
#define W_WQ   16
#define W_BQ   48
#define W_WK   56
#define W_BK   88
#define W_WV   96
#define W_BV   128
#define W_LN2G 136
#define W_LN2B 144
#define W_W1   152
#define W_B1   408
#define W_W2   440
#define W_B2   696

__global__ void __launch_bounds__(256, 2) vit_blocks_kernel(
    const float* __restrict__ ln1_g, const float* __restrict__ ln1_b,
    const float* __restrict__ Wq, const float* __restrict__ bq,
    const float* __restrict__ Wk, const float* __restrict__ bk,
    const float* __restrict__ Wv, const float* __restrict__ bv,
    const float* __restrict__ ln2_g, const float* __restrict__ ln2_b,
    const float* __restrict__ W1, const float* __restrict__ b1,
    const float* __restrict__ W2, const float* __restrict__ b2,
    const float* __restrict__ Wf, const float* __restrict__ bf,
    float* __restrict__ out)
{
    __shared__ float  xs[SEQ * 9];        // row stride 9 (bank pad)
    __shared__ float4 q4[2 * SEQ];
    __shared__ float4 k4[2 * SEQ];
    __shared__ float4 v4[2 * SEQ];
    __shared__ float  ws[704];
    __shared__ float  red[8][8];          // layer-2 attention partials

    const int n   = blockIdx.x;
    const int tid = threadIdx.x;

    for (int i = tid; i < SEQ * HID; i += 256)
        xs[(i >> 3) * 9 + (i & 7)] = g_x[(size_t)n * SEQ * HID + i];

    for (int l = 0; l < 2; l++) {
        __syncthreads();
        // ---- stage per-layer weights ----
        if (tid < 8) {
            ws[W_LN1G + tid] = ln1_g[l * 8 + tid];
            ws[W_LN1B + tid] = ln1_b[l * 8 + tid];
            ws[W_BQ   + tid] = bq[l * 8 + tid];
            ws[W_BK   + tid] = bk[l * 8 + tid];
            ws[W_BV   + tid] = bv[l * 8 + tid];
            ws[W_LN2G + tid] = ln2_g[l * 8 + tid];
            ws[W_LN2B + tid] = ln2_b[l * 8 + tid];
            ws[W_B2   + tid] = b2[l * 8 + tid];
        }
        if (tid < 32) {
            ws[W_WQ + tid] = Wq[l * 32 + tid];
            ws[W_WK + tid] = Wk[l * 32 + tid];
            ws[W_WV + tid] = Wv[l * 32 + tid];
            ws[W_B1 + tid] = b1[l * 32 + tid];
        }
        ws[W_W1 + tid] = W1[l * 256 + tid];
        ws[W_W2 + tid] = W2[l * 256 + tid];
        __syncthreads();

        // ---- LN1 + QKV (q pre-scaled by 1/sqrt(DH)=0.5) ----
        for (int t = tid; t < SEQ; t += 256) {
            float x8[8]; float m = 0.f;
#pragma unroll
            for (int e = 0; e < 8; e++) { x8[e] = xs[t * 9 + e]; m += x8[e]; }
            m *= 0.125f;
            float var = 0.f;
#pragma unroll
            for (int e = 0; e < 8; e++) { float dd = x8[e] - m; var += dd * dd; }
            float inv = rsqrtf(var * 0.125f + EPS_LN);
            float h[8];
#pragma unroll
            for (int e = 0; e < 8; e++)
                h[e] = (x8[e] - m) * inv * ws[W_LN1G + e] + ws[W_LN1B + e];
#pragma unroll
            for (int hh = 0; hh < 2; hh++) {
                float qv[4], kv[4], vv[4];
#pragma unroll
                for (int e = 0; e < 4; e++) {
                    qv[e] = ws[W_BQ + hh * 4 + e];
                    kv[e] = ws[W_BK + hh * 4 + e];
                    vv[e] = ws[W_BV + hh * 4 + e];
                }
#pragma unroll
                for (int d = 0; d < 4; d++) {
                    float hv = h[hh * 4 + d];
#pragma unroll
                    for (int e = 0; e < 4; e++) {
                        qv[e] += hv * ws[W_WQ + hh * 16 + d * 4 + e];
                        kv[e] += hv * ws[W_WK + hh * 16 + d * 4 + e];
                        vv[e] += hv * ws[W_WV + hh * 16 + d * 4 + e];
                    }
                }
                q4[hh * SEQ + t] = make_float4(qv[0] * 0.5f, qv[1] * 0.5f,
                                               qv[2] * 0.5f, qv[3] * 0.5f);
                k4[hh * SEQ + t] = make_float4(kv[0], kv[1], kv[2], kv[3]);
                v4[hh * SEQ + t] = make_float4(vv[0], vv[1], vv[2], vv[3]);
            }
        }
        __syncthreads();

        // ---- attention (logits tiny -> exp without max-subtraction) ----
        if (l == 0) {
            // full: one thread per (head, query row)
            for (int row = tid; row < 2 * SEQ; row += 256) {
                const int hh   = (row >= SEQ) ? 1 : 0;
                const int sidx = row - hh * SEQ;
                const float4 qv = q4[hh * SEQ + sidx];
                const float4* kb = k4 + hh * SEQ;
                const float4* vb = v4 + hh * SEQ;
                float  ssum = 0.f;
                float4 o = make_float4(0.f, 0.f, 0.f, 0.f);
#pragma unroll 4
                for (int t = 0; t < SEQ; t++) {
                    float4 kt = kb[t];
                    float dot = fmaf(qv.x, kt.x, fmaf(qv.y, kt.y,
                                fmaf(qv.z, kt.z, qv.w * kt.w)));
                    float pp = __expf(dot);
                    float4 vt = vb[t];
                    o.x = fmaf(pp, vt.x, o.x); o.y = fmaf(pp, vt.y, o.y);
                    o.z = fmaf(pp, vt.z, o.z); o.w = fmaf(pp, vt.w, o.w);
                    ssum += pp;
                }
                float invs = 1.f / ssum;
                float* xr = xs + sidx * 9 + hh * 4;
                xr[0] += o.x * invs; xr[1] += o.y * invs;
                xr[2] += o.z * invs; xr[3] += o.w * invs;
            }
        } else {
            // only query row 0 of each head matters downstream.
            const int hh = tid >> 7;          // 0/1, warps 0-3 / 4-7
            const int tl = tid & 127;
            const float4 qv = q4[hh * SEQ];
            const float4* kb = k4 + hh * SEQ;
            const float4* vb = v4 + hh * SEQ;
            float  ssum = 0.f;
            float4 o = make_float4(0.f, 0.f, 0.f, 0.f);
            for (int t = tl; t < SEQ; t += 128) {
                float4 kt = kb[t];
                float dot = fmaf(qv.x, kt.x, fmaf(qv.y, kt.y,
                            fmaf(qv.z, kt.z, qv.w * kt.w)));
                float pp = __expf(dot);
                float4 vt = vb[t];
                o.x = fmaf(pp, vt.x, o.x); o.y = fmaf(pp, vt.y, o.y);
                o.z = fmaf(pp, vt.z, o.z); o.w = fmaf(pp, vt.w, o.w);
                ssum += pp;
            }
#pragma unroll
            for (int off = 16; off >= 1; off >>= 1) {
                o.x += __shfl_xor_sync(0xffffffffu, o.x, off);
                o.y += __shfl_xor_sync(0xffffffffu, o.y, off);
                o.z += __shfl_xor_sync(0xffffffffu, o.z, off);
                o.w += __shfl_xor_sync(0xffffffffu, o.w, off);
                ssum += __shfl_xor_sync(0xffffffffu, ssum, off);
            }
            int wid = tid >> 5;
            if ((tid & 31) == 0) {
                red[wid][0] = o.x; red[wid][1] = o.y;
                red[wid][2] = o.z; red[wid][3] = o.w;
                red[wid][4] = ssum;
            }
            __syncthreads();
            if (tid < 2) {
                float O0 = 0.f, O1 = 0.f, O2 = 0.f, O3 = 0.f, S = 0.f;
#pragma unroll
                for (int w = 0; w < 4; w++) {
                    int r = tid * 4 + w;
                    O0 += red[r][0]; O1 += red[r][1];
                    O2 += red[r][2]; O3 += red[r][3]; S += red[r][4];
                }
                float invs = 1.f / S;
                float* xr = xs + tid * 4;   // token 0, head tid
                xr[0] += O0 * invs; xr[1] += O1 * invs;
                xr[2] += O2 * invs; xr[3] += O3 * invs;
            }
        }
        __syncthreads();

        // ---- LN2 + MLP (exact GELU) ----
        if (l == 0) {
            for (int t = tid; t < SEQ; t += 256) {
                float x8[8]; float m = 0.f;
#pragma unroll
                for (int e = 0; e < 8; e++) { x8[e] = xs[t * 9 + e]; m += x8[e]; }
                m *= 0.125f;
                float var = 0.f;
#pragma unroll
                for (int e = 0; e < 8; e++) { float dd = x8[e] - m; var += dd * dd; }
                float inv = rsqrtf(var * 0.125f + EPS_LN);
                float h[8];
#pragma unroll
                for (int e = 0; e < 8; e++)
                    h[e] = (x8[e] - m) * inv * ws[W_LN2G + e] + ws[W_LN2B + e];
                float o8[8];
#pragma unroll
                for (int e = 0; e < 8; e++) o8[e] = ws[W_B2 + e];
#pragma unroll 8
                for (int j = 0; j < MLPD; j++) {
                    float a = ws[W_B1 + j];
#pragma unroll
                    for (int d = 0; d < 8; d++) a += h[d] * ws[W_W1 + d * 32 + j];
                    float g = 0.5f * a * (1.f + erff(a * 0.70710678118f));
#pragma unroll
                    for (int e = 0; e < 8; e++) o8[e] += g * ws[W_W2 + j * 8 + e];
                }
#pragma unroll
                for (int e = 0; e < 8; e++) xs[t * 9 + e] = x8[e] + o8[e];
            }
        } else {
            // only token 0: warp 0, one MLP column per lane
            if (tid < 32) {
                float x8[8]; float m = 0.f;
#pragma unroll
                for (int e = 0; e < 8; e++) { x8[e] = xs[e]; m += x8[e]; }
                m *= 0.125f;
                float var = 0.f;
#pragma unroll
                for (int e = 0; e < 8; e++) { float dd = x8[e] - m; var += dd * dd; }
                float inv = rsqrtf(var * 0.125f + EPS_LN);
                float h[8];
#pragma unroll
                for (int e = 0; e < 8; e++)
                    h[e] = (x8[e] - m) * inv * ws[W_LN2G + e] + ws[W_LN2B + e];
                float a = ws[W_B1 + tid];
#pragma unroll
                for (int d = 0; d < 8; d++) a += h[d] * ws[W_W1 + d * 32 + tid];
                float g = 0.5f * a * (1.f + erff(a * 0.70710678118f));
                float o8[8];
#pragma unroll
                for (int e = 0; e < 8; e++) o8[e] = g * ws[W_W2 + tid * 8 + e];
#pragma unroll
                for (int off = 16; off >= 1; off >>= 1)
#pragma unroll
                    for (int e = 0; e < 8; e++)
                        o8[e] += __shfl_xor_sync(0xffffffffu, o8[e], off);
                if (tid == 0) {
#pragma unroll
                    for (int e = 0; e < 8; e++)
                        xs[e] = x8[e] + o8[e] + ws[W_B2 + e];
                }
            }
        }
    }
    __syncthreads();

    // ---- head: out[n] = x[0] @ Wf + bf ----
    if (tid < DIMOUT) {
        float a = bf[tid];
#pragma unroll
        for (int e = 0; e < 8; e++) a += xs[e] * Wf[e * DIMOUT + tid];
        out[n * DIMOUT + tid] = a;
    }
}

// ======================================================================
extern "C" void kernel_launch(void* const* d_in, const int* in_sizes, int n_in,
                              void* d_out, int out_size)
{
    const float* images    = (const float*)d_in[0];
    const int*   labels    = (const int*)  d_in[1];
    const float* Wm        = (const float*)d_in[2];
    const float* bm        = (const float*)d_in[3];
    const float* cls_table = (const float*)d_in[4];
    const float* pe        = (const float*)d_in[5];
    const float* ln1_g     = (const float*)d_in[6];
    const float* ln1_b     = (const float*)d_in[7];
    const float* Wq        = (const float*)d_in[8];
    const float* bq        = (const float*)d_in[9];
    const float* Wk        = (const float*)d_in[10];
    const float* bk        = (const float*)d_in[11];
    const float* Wv        = (const float*)d_in[12];
    const float* bv        = (const float*)d_in[13];
    const float* ln2_g     = (const float*)d_in[14];
    const float* ln2_b     = (const float*)d_in[15];
    const float* W1        = (const float*)d_in[16];
    const float* b1        = (const float*)d_in[17];
    const float* W2        = (const float*)d_in[18];
    const float* b2        = (const float*)d_in[19];
    const float* Wf        = (const float*)d_in[20];
    const float* bf        = (const float*)d_in[21];
    float* out = (float*)d_out;

    dim3 gridA(NPATCH, N_IMG);
    patch_embed_kernel<<<gridA, 128>>>(images, labels, Wm, bm, cls_table, pe);

    vit_blocks_kernel<<<N_IMG, 256>>>(ln1_g, ln1_b, Wq, bq, Wk, bk, Wv, bv,
                                      ln2_g, ln2_b, W1, b1, W2, b2, Wf, bf, out);
}

// round 3
// speedup vs baseline: 2.1823x; 1.4035x over previous
#include <cuda_runtime.h>

// ---------------- problem constants ----------------
#define N_IMG   512
#define C_CH    3
#define SDIM    224
#define NPATCH  16
#define PS      14
#define INPUT_D 588        // 3*14*14
#define HID     8
#define HEADS   2
#define DH      4
#define SEQ     257
#define MLPD    32
#define DIMOUT  10
#define EPS_LN  1e-5f
#define NG      8          // images per patch-embed block

// scratch: token/state buffer x[n][257][8]
__device__ float g_x[N_IMG * SEQ * HID];

// ---------------- packed f32x2 helpers ----------------
__device__ __forceinline__ void fma2(unsigned long long& d,
                                     unsigned long long a, unsigned long long b) {
    asm("fma.rn.f32x2 %0, %1, %2, %0;" : "+l"(d) : "l"(a), "l"(b));
}
__device__ __forceinline__ unsigned long long add2(unsigned long long a,
                                                   unsigned long long b) {
    unsigned long long r;
    asm("add.rn.f32x2 %0, %1, %2;" : "=l"(r) : "l"(a), "l"(b));
    return r;
}
__device__ __forceinline__ unsigned long long packdup(float v) {
    unsigned long long r;
    asm("mov.b64 %0, {%1, %1};" : "=l"(r) : "f"(v));
    return r;
}
__device__ __forceinline__ float2 unpack2(unsigned long long v) {
    float2 f;
    asm("mov.b64 {%0, %1}, %2;" : "=f"(f.x), "=f"(f.y) : "l"(v));
    return f;
}
// dot of two packed 4-vectors, returns scalar sum of 4 products
__device__ __forceinline__ float dot4p(unsigned long long qxy, unsigned long long qzw,
                                       unsigned long long kxy, unsigned long long kzw) {
    float r;
    asm("{\n\t"
        ".reg .b64 t;\n\t"
        ".reg .f32 lo, hi;\n\t"
        "mul.rn.f32x2 t, %1, %3;\n\t"
        "fma.rn.f32x2 t, %2, %4, t;\n\t"
        "mov.b64 {lo, hi}, t;\n\t"
        "add.f32 %0, lo, hi;\n\t"
        "}" : "=f"(r) : "l"(qxy), "l"(qzw), "l"(kxy), "l"(kzw));
    return r;
}
__device__ __forceinline__ float ex2f(float x) {
    float r;
    asm("ex2.approx.f32 %0, %1;" : "=f"(r) : "f"(x));
    return r;
}

// ---------------- cp.async helpers ----------------
__device__ __forceinline__ void cp16(float* s, const float* g) {
    unsigned sa = (unsigned)__cvta_generic_to_shared(s);
    asm volatile("cp.async.cg.shared.global [%0], [%1], 16;" :: "r"(sa), "l"(g));
}
#define CP_COMMIT() asm volatile("cp.async.commit_group;")
#define CP_WAIT0()  asm volatile("cp.async.wait_group 0;")
#define CP_WAIT1()  asm volatile("cp.async.wait_group 1;")

// ======================================================================
// Kernel A v3: patchify + linear proj + pe + cls.
// grid (16 py, 64 ig) x 128 thr. Each block: 8 images, one stripe row.
// Wm staged once; image stripes double-buffered via cp.async.
// thread: dq = warp (0..3), lane = s*4 + pg.
// ======================================================================
__global__ void __launch_bounds__(128) patch_embed_kernel(
    const float* __restrict__ images, const int* __restrict__ labels,
    const float* __restrict__ Wm, const float* __restrict__ bm,
    const float* __restrict__ cls_table, const float* __restrict__ pe)
{
    __shared__ float wm_s[INPUT_D * HID];      // 18816 B
    __shared__ float xstripe[2][PS * SDIM];    // 2 x 12544 B
    __shared__ float sacc[4][16 * 9];          // 2304 B

    const int py  = blockIdx.x;
    const int n0  = blockIdx.y * NG;
    const int tid = threadIdx.x;
    const int lane = tid & 31;
    const int dq   = tid >> 5;
    const int pg   = lane & 3;
    const int s    = lane >> 2;

    // prefetch first stripe (img 0, ch 0)
    {
        const float* src = images + (size_t)n0 * (C_CH * SDIM * SDIM) + py * (PS * SDIM);
        for (int j = tid; j < PS * SDIM / 4; j += 128) cp16(&xstripe[0][j * 4], src + j * 4);
        CP_COMMIT();
    }

    // stage Wm (float4)
    {
        const float4* src = reinterpret_cast<const float4*>(Wm);
        float4*       dst = reinterpret_cast<float4*>(wm_s);
        for (int i = tid; i < INPUT_D * HID / 4; i += 128) dst[i] = src[i];
    }

    // cls tokens
    if (py == 0 && tid < NG * 8) {
        int img = tid >> 3, e = tid & 7;
        int lab = labels[n0 + img];
        g_x[(size_t)(n0 + img) * SEQ * HID + e] = cls_table[lab * 8 + e] + pe[e];
    }

    unsigned long long acc[4][4];   // [patch-group j][pair] packed f32x2
#pragma unroll
    for (int j = 0; j < 4; j++)
#pragma unroll
        for (int p2 = 0; p2 < 4; p2++) acc[j][p2] = 0ull;

    for (int ph = 0; ph < NG * C_CH; ph++) {
        __syncthreads();   // previous compute done block-wide before buffer overwrite
        if (ph + 1 < NG * C_CH) {
            int img = (ph + 1) / 3, c = (ph + 1) % 3;
            const float* src = images + (size_t)(n0 + img) * (C_CH * SDIM * SDIM)
                                      + c * (SDIM * SDIM) + py * (PS * SDIM);
            float* dst = xstripe[(ph + 1) & 1];
            for (int j = tid; j < PS * SDIM / 4; j += 128) cp16(dst + j * 4, src + j * 4);
            CP_COMMIT();
            CP_WAIT1();
        } else {
            CP_WAIT0();
        }
        __syncthreads();   // stripe[ph] visible to all

        // ---- compute phase ph: img = ph/3, channel c = ph%3 ----
        {
            const int c = ph % 3;
            const float* xb = xstripe[ph & 1];
            int dl = dq * 56 + s;
            int r  = dl / PS;
            int q  = dl - r * PS;
#pragma unroll
            for (int k = 0; k < 7; k++) {
                if (dl < 196) {
                    const ulonglong2* w2 =
                        reinterpret_cast<const ulonglong2*>(wm_s + (c * 196 + dl) * 8);
                    ulonglong2 wa = w2[0], wb = w2[1];
                    int base = r * SDIM + q;
#pragma unroll
                    for (int j = 0; j < 4; j++) {
                        unsigned long long xv2 = packdup(xb[base + (pg + 4 * j) * PS]);
                        fma2(acc[j][0], xv2, wa.x);
                        fma2(acc[j][1], xv2, wa.y);
                        fma2(acc[j][2], xv2, wb.x);
                        fma2(acc[j][3], xv2, wb.y);
                    }
                }
                dl += 8; q += 8;
                if (q >= PS) { q -= PS; r++; }
            }
        }

        // ---- finalize image after its last channel ----
        if (ph % 3 == 2) {
            const int img = ph / 3;
            // reduce over s (lane bits 2..4)
#pragma unroll
            for (int off = 16; off >= 4; off >>= 1)
#pragma unroll
                for (int j = 0; j < 4; j++)
#pragma unroll
                    for (int p2 = 0; p2 < 4; p2++)
                        acc[j][p2] = add2(acc[j][p2],
                                          __shfl_xor_sync(0xffffffffu, acc[j][p2], off));
            if (s == 0) {
#pragma unroll
                for (int j = 0; j < 4; j++) {
                    int p = pg + 4 * j;
#pragma unroll
                    for (int p2 = 0; p2 < 4; p2++) {
                        float2 f = unpack2(acc[j][p2]);
                        sacc[dq][p * 9 + p2 * 2]     = f.x;
                        sacc[dq][p * 9 + p2 * 2 + 1] = f.y;
                    }
                }
            }
#pragma unroll
            for (int j = 0; j < 4; j++)
#pragma unroll
                for (int p2 = 0; p2 < 4; p2++) acc[j][p2] = 0ull;
            __syncthreads();
            {
                int p = tid >> 3, e = tid & 7;
                float sum = sacc[0][p * 9 + e] + sacc[1][p * 9 + e]
                          + sacc[2][p * 9 + e] + sacc[3][p * 9 + e];
                int tok = 1 + py * 16 + p;
                g_x[((size_t)(n0 + img) * SEQ + tok) * HID + e] =
                    sum + __ldg(bm + e) + __ldg(pe + tok * 8 + e);
            }
        }
    }
}

// ======================================================================
// Kernel B v3: 2-layer transformer + head, one block per image.
// packed-f32x2 attention, ex2-domain softmax, cooperative tails.
// ======================================================================

#define W_LN1G 0
#define W_LN1B 8
#define W_WQ   16
#define W_BQ   48
#define W_WK   56
#define W_BK   88
#define W_WV   96
#define W_BV   128
#define W_LN2G 136
#define W_LN2B 144
#define W_W1   152
#define W_B1   408
#define W_W2   440
#define W_B2   696

#define QSCALE 0.72134752044f   /* 0.5 * log2(e) : folds attn scale + exp->ex2 */

__global__ void __launch_bounds__(256, 3) vit_blocks_kernel(
    const float* __restrict__ ln1_g, const float* __restrict__ ln1_b,
    const float* __restrict__ Wq, const float* __restrict__ bq,
    const float* __restrict__ Wk, const float* __restrict__ bk,
    const float* __restrict__ Wv, const float* __restrict__ bv,
    const float* __restrict__ ln2_g, const float* __restrict__ ln2_b,
    const float* __restrict__ W1, const float* __restrict__ b1,
    const float* __restrict__ W2, const float* __restrict__ b2,
    const float* __restrict__ Wf, const float* __restrict__ bf,
    float* __restrict__ out)
{
    __shared__ float  xs[SEQ * 9];        // row stride 9 (bank pad)
    __shared__ float4 q4[2 * SEQ];
    __shared__ float4 k4[2 * SEQ];
    __shared__ float4 v4[2 * SEQ];
    __shared__ float  ws[704];
    __shared__ float  red[8][8];

    const int n   = blockIdx.x;
    const int tid = threadIdx.x;

    for (int i = tid; i < SEQ * HID; i += 256)
        xs[(i >> 3) * 9 + (i & 7)] = g_x[(size_t)n * SEQ * HID + i];

    for (int l = 0; l < 2; l++) {
        __syncthreads();
        if (tid < 8) {
            ws[W_LN1G + tid] = ln1_g[l * 8 + tid];
            ws[W_LN1B + tid] = ln1_b[l * 8 + tid];
            ws[W_BQ   + tid] = bq[l * 8 + tid];
            ws[W_BK   + tid] = bk[l * 8 + tid];
            ws[W_BV   + tid] = bv[l * 8 + tid];
            ws[W_LN2G + tid] = ln2_g[l * 8 + tid];
            ws[W_LN2B + tid] = ln2_b[l * 8 + tid];
            ws[W_B2   + tid] = b2[l * 8 + tid];
        }
        if (tid < 32) {
            ws[W_WQ + tid] = Wq[l * 32 + tid];
            ws[W_WK + tid] = Wk[l * 32 + tid];
            ws[W_WV + tid] = Wv[l * 32 + tid];
            ws[W_B1 + tid] = b1[l * 32 + tid];
        }
        ws[W_W1 + tid] = W1[l * 256 + tid];
        ws[W_W2 + tid] = W2[l * 256 + tid];
        __syncthreads();

        // ---- LN1 + QKV (q pre-scaled into log2 domain) ----
        for (int t = tid; t < SEQ; t += 256) {
            float x8[8]; float m = 0.f;
#pragma unroll
            for (int e = 0; e < 8; e++) { x8[e] = xs[t * 9 + e]; m += x8[e]; }
            m *= 0.125f;
            float var = 0.f;
#pragma unroll
            for (int e = 0; e < 8; e++) { float dd = x8[e] - m; var += dd * dd; }
            float inv = rsqrtf(var * 0.125f + EPS_LN);
            float h[8];
#pragma unroll
            for (int e = 0; e < 8; e++)
                h[e] = (x8[e] - m) * inv * ws[W_LN1G + e] + ws[W_LN1B + e];
            const bool needq = (l == 0) || (t == 0);
#pragma unroll
            for (int hh = 0; hh < 2; hh++) {
                float qv[4], kv[4], vv[4];
#pragma unroll
                for (int e = 0; e < 4; e++) {
                    qv[e] = ws[W_BQ + hh * 4 + e];
                    kv[e] = ws[W_BK + hh * 4 + e];
                    vv[e] = ws[W_BV + hh * 4 + e];
                }
#pragma unroll
                for (int d = 0; d < 4; d++) {
                    float hv = h[hh * 4 + d];
#pragma unroll
                    for (int e = 0; e < 4; e++) {
                        qv[e] += hv * ws[W_WQ + hh * 16 + d * 4 + e];
                        kv[e] += hv * ws[W_WK + hh * 16 + d * 4 + e];
                        vv[e] += hv * ws[W_WV + hh * 16 + d * 4 + e];
                    }
                }
                if (needq)
                    q4[hh * SEQ + t] = make_float4(qv[0] * QSCALE, qv[1] * QSCALE,
                                                   qv[2] * QSCALE, qv[3] * QSCALE);
                k4[hh * SEQ + t] = make_float4(kv[0], kv[1], kv[2], kv[3]);
                v4[hh * SEQ + t] = make_float4(vv[0], vv[1], vv[2], vv[3]);
            }
        }
        __syncthreads();

        // ---- attention (tiny logits -> no max subtraction; ex2 domain) ----
        if (l == 0) {
            // rows 0..511: one thread per (head, query); 2 clean passes
            for (int row = tid; row < 512; row += 256) {
                const int hh   = (row >= SEQ) ? 1 : 0;
                const int sidx = row - hh * SEQ;
                const ulonglong2 qq = *reinterpret_cast<const ulonglong2*>(q4 + hh * SEQ + sidx);
                const ulonglong2* kb = reinterpret_cast<const ulonglong2*>(k4 + hh * SEQ);
                const ulonglong2* vb = reinterpret_cast<const ulonglong2*>(v4 + hh * SEQ);
                unsigned long long oxy = 0ull, ozw = 0ull;
                float ssum = 0.f;
#pragma unroll 2
                for (int t = 0; t < SEQ; t++) {
                    ulonglong2 kt = kb[t];
                    float pp = ex2f(dot4p(qq.x, qq.y, kt.x, kt.y));
                    ulonglong2 vt = vb[t];
                    unsigned long long pp2 = packdup(pp);
                    fma2(oxy, pp2, vt.x);
                    fma2(ozw, pp2, vt.y);
                    ssum += pp;
                }
                float invs = 1.f / ssum;
                float2 f01 = unpack2(oxy), f23 = unpack2(ozw);
                float* xr = xs + sidx * 9 + hh * 4;
                xr[0] += f01.x * invs; xr[1] += f01.y * invs;
                xr[2] += f23.x * invs; xr[3] += f23.y * invs;
            }
            // tail rows 512,513 (head 1, sidx 255/256): cooperative warps 0,1
            {
                const int wid = tid >> 5, lanei = tid & 31;
                if (wid < 2) {
                    const int sidx = 255 + wid;
                    const ulonglong2 qq = *reinterpret_cast<const ulonglong2*>(q4 + SEQ + sidx);
                    const ulonglong2* kb = reinterpret_cast<const ulonglong2*>(k4 + SEQ);
                    const ulonglong2* vb = reinterpret_cast<const ulonglong2*>(v4 + SEQ);
                    unsigned long long oxy = 0ull, ozw = 0ull;
                    float ssum = 0.f;
                    for (int t = lanei; t < SEQ; t += 32) {
                        ulonglong2 kt = kb[t];
                        float pp = ex2f(dot4p(qq.x, qq.y, kt.x, kt.y));
                        ulonglong2 vt = vb[t];
                        unsigned long long pp2 = packdup(pp);
                        fma2(oxy, pp2, vt.x);
                        fma2(ozw, pp2, vt.y);
                        ssum += pp;
                    }
#pragma unroll
                    for (int off = 16; off >= 1; off >>= 1) {
                        oxy = add2(oxy, __shfl_xor_sync(0xffffffffu, oxy, off));
                        ozw = add2(ozw, __shfl_xor_sync(0xffffffffu, ozw, off));
                        ssum += __shfl_xor_sync(0xffffffffu, ssum, off);
                    }
                    if (lanei == 0) {
                        float invs = 1.f / ssum;
                        float2 f01 = unpack2(oxy), f23 = unpack2(ozw);
                        float* xr = xs + sidx * 9 + 4;
                        xr[0] += f01.x * invs; xr[1] += f01.y * invs;
                        xr[2] += f23.x * invs; xr[3] += f23.y * invs;
                    }
                }
            }
        } else {
            // only query row 0 of each head matters downstream
            const int hh = tid >> 7;
            const int tl = tid & 127;
            const ulonglong2 qq = *reinterpret_cast<const ulonglong2*>(q4 + hh * SEQ);
            const ulonglong2* kb = reinterpret_cast<const ulonglong2*>(k4 + hh * SEQ);
            const ulonglong2* vb = reinterpret_cast<const ulonglong2*>(v4 + hh * SEQ);
            unsigned long long oxy = 0ull, ozw = 0ull;
            float ssum = 0.f;
            for (int t = tl; t < SEQ; t += 128) {
                ulonglong2 kt = kb[t];
                float pp = ex2f(dot4p(qq.x, qq.y, kt.x, kt.y));
                ulonglong2 vt = vb[t];
                unsigned long long pp2 = packdup(pp);
                fma2(oxy, pp2, vt.x);
                fma2(ozw, pp2, vt.y);
                ssum += pp;
            }
#pragma unroll
            for (int off = 16; off >= 1; off >>= 1) {
                oxy = add2(oxy, __shfl_xor_sync(0xffffffffu, oxy, off));
                ozw = add2(ozw, __shfl_xor_sync(0xffffffffu, ozw, off));
                ssum += __shfl_xor_sync(0xffffffffu, ssum, off);
            }
            int wid = tid >> 5;
            if ((tid & 31) == 0) {
                float2 f01 = unpack2(oxy), f23 = unpack2(ozw);
                red[wid][0] = f01.x; red[wid][1] = f01.y;
                red[wid][2] = f23.x; red[wid][3] = f23.y;
                red[wid][4] = ssum;
            }
            __syncthreads();
            if (tid < 2) {
                float O0 = 0.f, O1 = 0.f, O2 = 0.f, O3 = 0.f, S = 0.f;
#pragma unroll
                for (int w = 0; w < 4; w++) {
                    int r = tid * 4 + w;
                    O0 += red[r][0]; O1 += red[r][1];
                    O2 += red[r][2]; O3 += red[r][3]; S += red[r][4];
                }
                float invs = 1.f / S;
                float* xr = xs + tid * 4;
                xr[0] += O0 * invs; xr[1] += O1 * invs;
                xr[2] += O2 * invs; xr[3] += O3 * invs;
            }
        }
        __syncthreads();

        // ---- LN2 + MLP (exact GELU) ----
        if (l == 0) {
            for (int t = tid; t < SEQ; t += 256) {
                float x8[8]; float m = 0.f;
#pragma unroll
                for (int e = 0; e < 8; e++) { x8[e] = xs[t * 9 + e]; m += x8[e]; }
                m *= 0.125f;
                float var = 0.f;
#pragma unroll
                for (int e = 0; e < 8; e++) { float dd = x8[e] - m; var += dd * dd; }
                float inv = rsqrtf(var * 0.125f + EPS_LN);
                float h[8];
#pragma unroll
                for (int e = 0; e < 8; e++)
                    h[e] = (x8[e] - m) * inv * ws[W_LN2G + e] + ws[W_LN2B + e];
                float o8[8];
#pragma unroll
                for (int e = 0; e < 8; e++) o8[e] = ws[W_B2 + e];
#pragma unroll 8
                for (int j = 0; j < MLPD; j++) {
                    float a = ws[W_B1 + j];
#pragma unroll
                    for (int d = 0; d < 8; d++) a += h[d] * ws[W_W1 + d * 32 + j];
                    float g = 0.5f * a * (1.f + erff(a * 0.70710678118f));
#pragma unroll
                    for (int e = 0; e < 8; e++) o8[e] += g * ws[W_W2 + j * 8 + e];
                }
#pragma unroll
                for (int e = 0; e < 8; e++) xs[t * 9 + e] = x8[e] + o8[e];
            }
        } else {
            if (tid < 32) {
                float x8[8]; float m = 0.f;
#pragma unroll
                for (int e = 0; e < 8; e++) { x8[e] = xs[e]; m += x8[e]; }
                m *= 0.125f;
                float var = 0.f;
#pragma unroll
                for (int e = 0; e < 8; e++) { float dd = x8[e] - m; var += dd * dd; }
                float inv = rsqrtf(var * 0.125f + EPS_LN);
                float h[8];
#pragma unroll
                for (int e = 0; e < 8; e++)
                    h[e] = (x8[e] - m) * inv * ws[W_LN2G + e] + ws[W_LN2B + e];
                float a = ws[W_B1 + tid];
#pragma unroll
                for (int d = 0; d < 8; d++) a += h[d] * ws[W_W1 + d * 32 + tid];
                float g = 0.5f * a * (1.f + erff(a * 0.70710678118f));
                float o8[8];
#pragma unroll
                for (int e = 0; e < 8; e++) o8[e] = g * ws[W_W2 + tid * 8 + e];
#pragma unroll
                for (int off = 16; off >= 1; off >>= 1)
#pragma unroll
                    for (int e = 0; e < 8; e++)
                        o8[e] += __shfl_xor_sync(0xffffffffu, o8[e], off);
                if (tid == 0) {
#pragma unroll
                    for (int e = 0; e < 8; e++)
                        xs[e] = x8[e] + o8[e] + ws[W_B2 + e];
                }
            }
        }
    }
    __syncthreads();

    if (tid < DIMOUT) {
        float a = bf[tid];
#pragma unroll
        for (int e = 0; e < 8; e++) a += xs[e] * Wf[e * DIMOUT + tid];
        out[n * DIMOUT + tid] = a;
    }
}

// ======================================================================
extern "C" void kernel_launch(void* const* d_in, const int* in_sizes, int n_in,
                              void* d_out, int out_size)
{
    const float* images    = (const float*)d_in[0];
    const int*   labels    = (const int*)  d_in[1];
    const float* Wm        = (const float*)d_in[2];
    const float* bm        = (const float*)d_in[3];
    const float* cls_table = (const float*)d_in[4];
    const float* pe        = (const float*)d_in[5];
    const float* ln1_g     = (const float*)d_in[6];
    const float* ln1_b     = (const float*)d_in[7];
    const float* Wq        = (const float*)d_in[8];
    const float* bq        = (const float*)d_in[9];
    const float* Wk        = (const float*)d_in[10];
    const float* bk        = (const float*)d_in[11];
    const float* Wv        = (const float*)d_in[12];
    const float* bv        = (const float*)d_in[13];
    const float* ln2_g     = (const float*)d_in[14];
    const float* ln2_b     = (const float*)d_in[15];
    const float* W1        = (const float*)d_in[16];
    const float* b1        = (const float*)d_in[17];
    const float* W2        = (const float*)d_in[18];
    const float* b2        = (const float*)d_in[19];
    const float* Wf        = (const float*)d_in[20];
    const float* bf        = (const float*)d_in[21];
    float* out = (float*)d_out;

    dim3 gridA(NPATCH, N_IMG / NG);
    patch_embed_kernel<<<gridA, 128>>>(images, labels, Wm, bm, cls_table, pe);

    vit_blocks_kernel<<<N_IMG, 256>>>(ln1_g, ln1_b, Wq, bq, Wk, bk, Wv, bv,
                                      ln2_g, ln2_b, W1, b1, W2, b2, Wf, bf, out);
}

// round 4
// speedup vs baseline: 2.2093x; 1.0124x over previous
#include <cuda_runtime.h>

// ---------------- problem constants ----------------
#define N_IMG   512
#define C_CH    3
#define SDIM    224
#define NPATCH  16
#define PS      14
#define INPUT_D 588        // 3*14*14
#define HID     8
#define HEADS   2
#define DH      4
#define SEQ     257
#define MLPD    32
#define DIMOUT  10
#define EPS_LN  1e-5f
#define NG      16         // images per patch-embed block

// scratch: token/state buffer x[n][257][8]
__device__ float g_x[N_IMG * SEQ * HID];

typedef unsigned long long u64;

// ---------------- packed f32x2 helpers ----------------
__device__ __forceinline__ void fma2(u64& d, u64 a, u64 b) {
    asm("fma.rn.f32x2 %0, %1, %2, %0;" : "+l"(d) : "l"(a), "l"(b));
}
__device__ __forceinline__ void mul2(u64& d, u64 a, u64 b) {
    asm("mul.rn.f32x2 %0, %1, %2;" : "=l"(d) : "l"(a), "l"(b));
}
__device__ __forceinline__ u64 add2(u64 a, u64 b) {
    u64 r;
    asm("add.rn.f32x2 %0, %1, %2;" : "=l"(r) : "l"(a), "l"(b));
    return r;
}
__device__ __forceinline__ u64 packdup(float v) {
    u64 r;
    asm("mov.b64 %0, {%1, %1};" : "=l"(r) : "f"(v));
    return r;
}
__device__ __forceinline__ u64 pack2(float lo, float hi) {
    u64 r;
    asm("mov.b64 %0, {%1, %2};" : "=l"(r) : "f"(lo), "f"(hi));
    return r;
}
__device__ __forceinline__ float2 unpack2(u64 v) {
    float2 f;
    asm("mov.b64 {%0, %1}, %2;" : "=f"(f.x), "=f"(f.y) : "l"(v));
    return f;
}
__device__ __forceinline__ float ex2f(float x) {
    float r;
    asm("ex2.approx.f32 %0, %1;" : "=f"(r) : "f"(x));
    return r;
}

// ---------------- cp.async helpers ----------------
__device__ __forceinline__ void cp16(float* s, const float* g) {
    unsigned sa = (unsigned)__cvta_generic_to_shared(s);
    asm volatile("cp.async.cg.shared.global [%0], [%1], 16;" :: "r"(sa), "l"(g));
}
#define CP_COMMIT() asm volatile("cp.async.commit_group;")
#define CP_WAIT0()  asm volatile("cp.async.wait_group 0;")
#define CP_WAIT1()  asm volatile("cp.async.wait_group 1;")

// ======================================================================
// Kernel A: patchify + linear proj + pe + cls.
// grid (16 py, 32 ig) x 128 thr. Each block: 16 images, one stripe row.
// Wm staged once; image stripes double-buffered via cp.async.
// ======================================================================
__global__ void __launch_bounds__(128) patch_embed_kernel(
    const float* __restrict__ images, const int* __restrict__ labels,
    const float* __restrict__ Wm, const float* __restrict__ bm,
    const float* __restrict__ cls_table, const float* __restrict__ pe)
{
    __shared__ float wm_s[INPUT_D * HID];      // 18816 B
    __shared__ float xstripe[2][PS * SDIM];    // 2 x 12544 B
    __shared__ float sacc[4][16 * 9];          // 2304 B

    const int py  = blockIdx.x;
    const int n0  = blockIdx.y * NG;
    const int tid = threadIdx.x;
    const int lane = tid & 31;
    const int dq   = tid >> 5;
    const int pg   = lane & 3;
    const int s    = lane >> 2;

    // prefetch first stripe (img 0, ch 0)
    {
        const float* src = images + (size_t)n0 * (C_CH * SDIM * SDIM) + py * (PS * SDIM);
        for (int j = tid; j < PS * SDIM / 4; j += 128) cp16(&xstripe[0][j * 4], src + j * 4);
        CP_COMMIT();
    }

    // stage Wm (float4)
    {
        const float4* src = reinterpret_cast<const float4*>(Wm);
        float4*       dst = reinterpret_cast<float4*>(wm_s);
        for (int i = tid; i < INPUT_D * HID / 4; i += 128) dst[i] = src[i];
    }

    // cls tokens (NG*8 = 128 threads)
    if (py == 0) {
        int img = tid >> 3, e = tid & 7;
        int lab = labels[n0 + img];
        g_x[(size_t)(n0 + img) * SEQ * HID + e] = cls_table[lab * 8 + e] + pe[e];
    }

    u64 acc[4][4];
#pragma unroll
    for (int j = 0; j < 4; j++)
#pragma unroll
        for (int p2 = 0; p2 < 4; p2++) acc[j][p2] = 0ull;

    for (int ph = 0; ph < NG * C_CH; ph++) {
        __syncthreads();
        if (ph + 1 < NG * C_CH) {
            int img = (ph + 1) / 3, c = (ph + 1) % 3;
            const float* src = images + (size_t)(n0 + img) * (C_CH * SDIM * SDIM)
                                      + c * (SDIM * SDIM) + py * (PS * SDIM);
            float* dst = xstripe[(ph + 1) & 1];
            for (int j = tid; j < PS * SDIM / 4; j += 128) cp16(dst + j * 4, src + j * 4);
            CP_COMMIT();
            CP_WAIT1();
        } else {
            CP_WAIT0();
        }
        __syncthreads();

        {
            const int c = ph % 3;
            const float* xb = xstripe[ph & 1];
            int dl = dq * 56 + s;
            int r  = dl / PS;
            int q  = dl - r * PS;
#pragma unroll
            for (int k = 0; k < 7; k++) {
                if (dl < 196) {
                    const ulonglong2* w2 =
                        reinterpret_cast<const ulonglong2*>(wm_s + (c * 196 + dl) * 8);
                    ulonglong2 wa = w2[0], wb = w2[1];
                    int base = r * SDIM + q;
#pragma unroll
                    for (int j = 0; j < 4; j++) {
                        u64 xv2 = packdup(xb[base + (pg + 4 * j) * PS]);
                        fma2(acc[j][0], xv2, wa.x);
                        fma2(acc[j][1], xv2, wa.y);
                        fma2(acc[j][2], xv2, wb.x);
                        fma2(acc[j][3], xv2, wb.y);
                    }
                }
                dl += 8; q += 8;
                if (q >= PS) { q -= PS; r++; }
            }
        }

        if (ph % 3 == 2) {
            const int img = ph / 3;
#pragma unroll
            for (int off = 16; off >= 4; off >>= 1)
#pragma unroll
                for (int j = 0; j < 4; j++)
#pragma unroll
                    for (int p2 = 0; p2 < 4; p2++)
                        acc[j][p2] = add2(acc[j][p2],
                                          __shfl_xor_sync(0xffffffffu, acc[j][p2], off));
            if (s == 0) {
#pragma unroll
                for (int j = 0; j < 4; j++) {
                    int p = pg + 4 * j;
#pragma unroll
                    for (int p2 = 0; p2 < 4; p2++) {
                        float2 f = unpack2(acc[j][p2]);
                        sacc[dq][p * 9 + p2 * 2]     = f.x;
                        sacc[dq][p * 9 + p2 * 2 + 1] = f.y;
                    }
                }
            }
#pragma unroll
            for (int j = 0; j < 4; j++)
#pragma unroll
                for (int p2 = 0; p2 < 4; p2++) acc[j][p2] = 0ull;
            __syncthreads();
            {
                int p = tid >> 3, e = tid & 7;
                float sum = sacc[0][p * 9 + e] + sacc[1][p * 9 + e]
                          + sacc[2][p * 9 + e] + sacc[3][p * 9 + e];
                int tok = 1 + py * 16 + p;
                g_x[((size_t)(n0 + img) * SEQ + tok) * HID + e] =
                    sum + __ldg(bm + e) + __ldg(pe + tok * 8 + e);
            }
        }
    }
}

// ======================================================================
// Kernel B: 2-layer transformer + head, one block per image.
// k/v in SoA so attention packs across t with f32x2 (no packing movs).
// ======================================================================

#define W_LN1G 0
#define W_LN1B 8
#define W_WQ   16
#define W_BQ   48
#define W_WK   56
#define W_BK   88
#define W_WV   96
#define W_BV   128
#define W_LN2G 136
#define W_LN2B 144
#define W_W1   152
#define W_B1   408
#define W_W2   440
#define W_B2   696

#define QSCALE 0.72134752044f   /* 0.5 * log2(e) */
#define TPAD   260              /* SoA component stride (16B-aligned) */

__global__ void __launch_bounds__(256, 4) vit_blocks_kernel(
    const float* __restrict__ ln1_g, const float* __restrict__ ln1_b,
    const float* __restrict__ Wq, const float* __restrict__ bq,
    const float* __restrict__ Wk, const float* __restrict__ bk,
    const float* __restrict__ Wv, const float* __restrict__ bv,
    const float* __restrict__ ln2_g, const float* __restrict__ ln2_b,
    const float* __restrict__ W1, const float* __restrict__ b1,
    const float* __restrict__ W2, const float* __restrict__ b2,
    const float* __restrict__ Wf, const float* __restrict__ bf,
    float* __restrict__ out)
{
    __shared__ float  xs[SEQ * 9];                     // stride-9 pad
    __shared__ __align__(16) float4 q4[2 * SEQ];
    __shared__ __align__(16) float  ksoa[2][4][TPAD];  // [head][comp][t]
    __shared__ __align__(16) float  vsoa[2][4][TPAD];
    __shared__ float  ws[704];
    __shared__ float  red[8][8];

    const int n   = blockIdx.x;
    const int tid = threadIdx.x;

    for (int i = tid; i < SEQ * HID; i += 256)
        xs[(i >> 3) * 9 + (i & 7)] = g_x[(size_t)n * SEQ * HID + i];

    for (int l = 0; l < 2; l++) {
        __syncthreads();
        if (tid < 8) {
            ws[W_LN1G + tid] = ln1_g[l * 8 + tid];
            ws[W_LN1B + tid] = ln1_b[l * 8 + tid];
            ws[W_BQ   + tid] = bq[l * 8 + tid];
            ws[W_BK   + tid] = bk[l * 8 + tid];
            ws[W_BV   + tid] = bv[l * 8 + tid];
            ws[W_LN2G + tid] = ln2_g[l * 8 + tid];
            ws[W_LN2B + tid] = ln2_b[l * 8 + tid];
            ws[W_B2   + tid] = b2[l * 8 + tid];
        }
        if (tid < 32) {
            ws[W_WQ + tid] = Wq[l * 32 + tid];
            ws[W_WK + tid] = Wk[l * 32 + tid];
            ws[W_WV + tid] = Wv[l * 32 + tid];
            ws[W_B1 + tid] = b1[l * 32 + tid];
        }
        ws[W_W1 + tid] = W1[l * 256 + tid];
        ws[W_W2 + tid] = W2[l * 256 + tid];
        __syncthreads();

        // ---- LN1 + QKV (q pre-scaled into log2 domain), k/v -> SoA ----
        for (int t = tid; t < SEQ; t += 256) {
            float x8[8]; float m = 0.f;
#pragma unroll
            for (int e = 0; e < 8; e++) { x8[e] = xs[t * 9 + e]; m += x8[e]; }
            m *= 0.125f;
            float var = 0.f;
#pragma unroll
            for (int e = 0; e < 8; e++) { float dd = x8[e] - m; var += dd * dd; }
            float inv = rsqrtf(var * 0.125f + EPS_LN);
            float h[8];
#pragma unroll
            for (int e = 0; e < 8; e++)
                h[e] = (x8[e] - m) * inv * ws[W_LN1G + e] + ws[W_LN1B + e];
            const bool needq = (l == 0) || (t == 0);
#pragma unroll
            for (int hh = 0; hh < 2; hh++) {
                float qv[4], kv[4], vv[4];
#pragma unroll
                for (int e = 0; e < 4; e++) {
                    qv[e] = ws[W_BQ + hh * 4 + e];
                    kv[e] = ws[W_BK + hh * 4 + e];
                    vv[e] = ws[W_BV + hh * 4 + e];
                }
#pragma unroll
                for (int d = 0; d < 4; d++) {
                    float hv = h[hh * 4 + d];
#pragma unroll
                    for (int e = 0; e < 4; e++) {
                        qv[e] += hv * ws[W_WQ + hh * 16 + d * 4 + e];
                        kv[e] += hv * ws[W_WK + hh * 16 + d * 4 + e];
                        vv[e] += hv * ws[W_WV + hh * 16 + d * 4 + e];
                    }
                }
                if (needq)
                    q4[hh * SEQ + t] = make_float4(qv[0] * QSCALE, qv[1] * QSCALE,
                                                   qv[2] * QSCALE, qv[3] * QSCALE);
#pragma unroll
                for (int e = 0; e < 4; e++) {
                    ksoa[hh][e][t] = kv[e];
                    vsoa[hh][e][t] = vv[e];
                }
            }
        }
        __syncthreads();

        // ---- attention ----
        if (l == 0) {
            for (int row = tid; row < 512; row += 256) {
                const int hh   = (row >= SEQ) ? 1 : 0;
                const int sidx = row - hh * SEQ;
                const float4 qv = q4[hh * SEQ + sidx];
                const u64 qx2 = packdup(qv.x), qy2 = packdup(qv.y),
                          qz2 = packdup(qv.z), qw2 = packdup(qv.w);
                const ulonglong2* kxp = reinterpret_cast<const ulonglong2*>(ksoa[hh][0]);
                const ulonglong2* kyp = reinterpret_cast<const ulonglong2*>(ksoa[hh][1]);
                const ulonglong2* kzp = reinterpret_cast<const ulonglong2*>(ksoa[hh][2]);
                const ulonglong2* kwp = reinterpret_cast<const ulonglong2*>(ksoa[hh][3]);
                const ulonglong2* vxp = reinterpret_cast<const ulonglong2*>(vsoa[hh][0]);
                const ulonglong2* vyp = reinterpret_cast<const ulonglong2*>(vsoa[hh][1]);
                const ulonglong2* vzp = reinterpret_cast<const ulonglong2*>(vsoa[hh][2]);
                const ulonglong2* vwp = reinterpret_cast<const ulonglong2*>(vsoa[hh][3]);

                u64 oX = 0, oY = 0, oZ = 0, oW = 0, s2 = 0;
                for (int t4 = 0; t4 < 64; t4++) {      // t = 0..255
                    ulonglong2 kx = kxp[t4], ky = kyp[t4], kz = kzp[t4], kw = kwp[t4];
                    u64 da, db;
                    mul2(da, qx2, kx.x); fma2(da, qy2, ky.x);
                    fma2(da, qz2, kz.x); fma2(da, qw2, kw.x);
                    mul2(db, qx2, kx.y); fma2(db, qy2, ky.y);
                    fma2(db, qz2, kz.y); fma2(db, qw2, kw.y);
                    float2 fa = unpack2(da), fb = unpack2(db);
                    u64 ppa = pack2(ex2f(fa.x), ex2f(fa.y));
                    u64 ppb = pack2(ex2f(fb.x), ex2f(fb.y));
                    ulonglong2 vx = vxp[t4], vy = vyp[t4], vz = vzp[t4], vw = vwp[t4];
                    fma2(oX, ppa, vx.x); fma2(oX, ppb, vx.y);
                    fma2(oY, ppa, vy.x); fma2(oY, ppb, vy.y);
                    fma2(oZ, ppa, vz.x); fma2(oZ, ppb, vz.y);
                    fma2(oW, ppa, vw.x); fma2(oW, ppb, vw.y);
                    s2 = add2(s2, add2(ppa, ppb));
                }
                float2 fX = unpack2(oX), fY = unpack2(oY),
                       fZ = unpack2(oZ), fW = unpack2(oW), fS = unpack2(s2);
                float ox = fX.x + fX.y, oy = fY.x + fY.y,
                      oz = fZ.x + fZ.y, ow = fW.x + fW.y, ssum = fS.x + fS.y;
                // tail t = 256
                {
                    float dt = fmaf(qv.x, ksoa[hh][0][256], fmaf(qv.y, ksoa[hh][1][256],
                               fmaf(qv.z, ksoa[hh][2][256], qv.w * ksoa[hh][3][256])));
                    float pp = ex2f(dt);
                    ox = fmaf(pp, vsoa[hh][0][256], ox);
                    oy = fmaf(pp, vsoa[hh][1][256], oy);
                    oz = fmaf(pp, vsoa[hh][2][256], oz);
                    ow = fmaf(pp, vsoa[hh][3][256], ow);
                    ssum += pp;
                }
                float invs = 1.f / ssum;
                float* xr = xs + sidx * 9 + hh * 4;
                xr[0] += ox * invs; xr[1] += oy * invs;
                xr[2] += oz * invs; xr[3] += ow * invs;
            }
            // tail rows 512,513 (head 1, sidx 255/256): cooperative warps 0,1
            {
                const int wid = tid >> 5, lanei = tid & 31;
                if (wid < 2) {
                    const int sidx = 255 + wid;
                    const float4 qv = q4[SEQ + sidx];
                    const float* kx = ksoa[1][0]; const float* ky = ksoa[1][1];
                    const float* kz = ksoa[1][2]; const float* kw = ksoa[1][3];
                    const float* vx = vsoa[1][0]; const float* vy = vsoa[1][1];
                    const float* vz = vsoa[1][2]; const float* vw = vsoa[1][3];
                    float ox = 0.f, oy = 0.f, oz = 0.f, ow = 0.f, ssum = 0.f;
                    for (int t = lanei; t < SEQ; t += 32) {
                        float dt = fmaf(qv.x, kx[t], fmaf(qv.y, ky[t],
                                   fmaf(qv.z, kz[t], qv.w * kw[t])));
                        float pp = ex2f(dt);
                        ox = fmaf(pp, vx[t], ox); oy = fmaf(pp, vy[t], oy);
                        oz = fmaf(pp, vz[t], oz); ow = fmaf(pp, vw[t], ow);
                        ssum += pp;
                    }
#pragma unroll
                    for (int off = 16; off >= 1; off >>= 1) {
                        ox += __shfl_xor_sync(0xffffffffu, ox, off);
                        oy += __shfl_xor_sync(0xffffffffu, oy, off);
                        oz += __shfl_xor_sync(0xffffffffu, oz, off);
                        ow += __shfl_xor_sync(0xffffffffu, ow, off);
                        ssum += __shfl_xor_sync(0xffffffffu, ssum, off);
                    }
                    if (lanei == 0) {
                        float invs = 1.f / ssum;
                        float* xr = xs + sidx * 9 + 4;
                        xr[0] += ox * invs; xr[1] += oy * invs;
                        xr[2] += oz * invs; xr[3] += ow * invs;
                    }
                }
            }
        } else {
            // only query row 0 of each head matters downstream
            const int hh = tid >> 7;
            const int tl = tid & 127;
            const float4 qv = q4[hh * SEQ];
            const float* kx = ksoa[hh][0]; const float* ky = ksoa[hh][1];
            const float* kz = ksoa[hh][2]; const float* kw = ksoa[hh][3];
            const float* vx = vsoa[hh][0]; const float* vy = vsoa[hh][1];
            const float* vz = vsoa[hh][2]; const float* vw = vsoa[hh][3];
            float ox = 0.f, oy = 0.f, oz = 0.f, ow = 0.f, ssum = 0.f;
            for (int t = tl; t < SEQ; t += 128) {
                float dt = fmaf(qv.x, kx[t], fmaf(qv.y, ky[t],
                           fmaf(qv.z, kz[t], qv.w * kw[t])));
                float pp = ex2f(dt);
                ox = fmaf(pp, vx[t], ox); oy = fmaf(pp, vy[t], oy);
                oz = fmaf(pp, vz[t], oz); ow = fmaf(pp, vw[t], ow);
                ssum += pp;
            }
#pragma unroll
            for (int off = 16; off >= 1; off >>= 1) {
                ox += __shfl_xor_sync(0xffffffffu, ox, off);
                oy += __shfl_xor_sync(0xffffffffu, oy, off);
                oz += __shfl_xor_sync(0xffffffffu, oz, off);
                ow += __shfl_xor_sync(0xffffffffu, ow, off);
                ssum += __shfl_xor_sync(0xffffffffu, ssum, off);
            }
            int wid = tid >> 5;
            if ((tid & 31) == 0) {
                red[wid][0] = ox; red[wid][1] = oy;
                red[wid][2] = oz; red[wid][3] = ow;
                red[wid][4] = ssum;
            }
            __syncthreads();
            if (tid < 2) {
                float O0 = 0.f, O1 = 0.f, O2 = 0.f, O3 = 0.f, S = 0.f;
#pragma unroll
                for (int w = 0; w < 4; w++) {
                    int r = tid * 4 + w;
                    O0 += red[r][0]; O1 += red[r][1];
                    O2 += red[r][2]; O3 += red[r][3]; S += red[r][4];
                }
                float invs = 1.f / S;
                float* xr = xs + tid * 4;
                xr[0] += O0 * invs; xr[1] += O1 * invs;
                xr[2] += O2 * invs; xr[3] += O3 * invs;
            }
        }
        __syncthreads();

        // ---- LN2 + MLP (exact GELU) ----
        if (l == 0) {
            for (int t = tid; t < SEQ; t += 256) {
                float x8[8]; float m = 0.f;
#pragma unroll
                for (int e = 0; e < 8; e++) { x8[e] = xs[t * 9 + e]; m += x8[e]; }
                m *= 0.125f;
                float var = 0.f;
#pragma unroll
                for (int e = 0; e < 8; e++) { float dd = x8[e] - m; var += dd * dd; }
                float inv = rsqrtf(var * 0.125f + EPS_LN);
                float h[8];
#pragma unroll
                for (int e = 0; e < 8; e++)
                    h[e] = (x8[e] - m) * inv * ws[W_LN2G + e] + ws[W_LN2B + e];
                float o8[8];
#pragma unroll
                for (int e = 0; e < 8; e++) o8[e] = ws[W_B2 + e];
#pragma unroll 8
                for (int j = 0; j < MLPD; j++) {
                    float a = ws[W_B1 + j];
#pragma unroll
                    for (int d = 0; d < 8; d++) a += h[d] * ws[W_W1 + d * 32 + j];
                    float g = 0.5f * a * (1.f + erff(a * 0.70710678118f));
#pragma unroll
                    for (int e = 0; e < 8; e++) o8[e] += g * ws[W_W2 + j * 8 + e];
                }
#pragma unroll
                for (int e = 0; e < 8; e++) xs[t * 9 + e] = x8[e] + o8[e];
            }
        } else {
            if (tid < 32) {
                float x8[8]; float m = 0.f;
#pragma unroll
                for (int e = 0; e < 8; e++) { x8[e] = xs[e]; m += x8[e]; }
                m *= 0.125f;
                float var = 0.f;
#pragma unroll
                for (int e = 0; e < 8; e++) { float dd = x8[e] - m; var += dd * dd; }
                float inv = rsqrtf(var * 0.125f + EPS_LN);
                float h[8];
#pragma unroll
                for (int e = 0; e < 8; e++)
                    h[e] = (x8[e] - m) * inv * ws[W_LN2G + e] + ws[W_LN2B + e];
                float a = ws[W_B1 + tid];
#pragma unroll
                for (int d = 0; d < 8; d++) a += h[d] * ws[W_W1 + d * 32 + tid];
                float g = 0.5f * a * (1.f + erff(a * 0.70710678118f));
                float o8[8];
#pragma unroll
                for (int e = 0; e < 8; e++) o8[e] = g * ws[W_W2 + tid * 8 + e];
#pragma unroll
                for (int off = 16; off >= 1; off >>= 1)
#pragma unroll
                    for (int e = 0; e < 8; e++)
                        o8[e] += __shfl_xor_sync(0xffffffffu, o8[e], off);
                if (tid == 0) {
#pragma unroll
                    for (int e = 0; e < 8; e++)
                        xs[e] = x8[e] + o8[e] + ws[W_B2 + e];
                }
            }
        }
    }
    __syncthreads();

    if (tid < DIMOUT) {
        float a = bf[tid];
#pragma unroll
        for (int e = 0; e < 8; e++) a += xs[e] * Wf[e * DIMOUT + tid];
        out[n * DIMOUT + tid] = a;
    }
}

// ======================================================================
extern "C" void kernel_launch(void* const* d_in, const int* in_sizes, int n_in,
                              void* d_out, int out_size)
{
    const float* images    = (const float*)d_in[0];
    const int*   labels    = (const int*)  d_in[1];
    const float* Wm        = (const float*)d_in[2];
    const float* bm        = (const float*)d_in[3];
    const float* cls_table = (const float*)d_in[4];
    const float* pe        = (const float*)d_in[5];
    const float* ln1_g     = (const float*)d_in[6];
    const float* ln1_b     = (const float*)d_in[7];
    const float* Wq        = (const float*)d_in[8];
    const float* bq        = (const float*)d_in[9];
    const float* Wk        = (const float*)d_in[10];
    const float* bk        = (const float*)d_in[11];
    const float* Wv        = (const float*)d_in[12];
    const float* bv        = (const float*)d_in[13];
    const float* ln2_g     = (const float*)d_in[14];
    const float* ln2_b     = (const float*)d_in[15];
    const float* W1        = (const float*)d_in[16];
    const float* b1        = (const float*)d_in[17];
    const float* W2        = (const float*)d_in[18];
    const float* b2        = (const float*)d_in[19];
    const float* Wf        = (const float*)d_in[20];
    const float* bf        = (const float*)d_in[21];
    float* out = (float*)d_out;

    dim3 gridA(NPATCH, N_IMG / NG);
    patch_embed_kernel<<<gridA, 128>>>(images, labels, Wm, bm, cls_table, pe);

    vit_blocks_kernel<<<N_IMG, 256>>>(ln1_g, ln1_b, Wq, bq, Wk, bk, Wv, bv,
                                      ln2_g, ln2_b, W1, b1, W2, b2, Wf, bf, out);
}